// round 1
// baseline (speedup 1.0000x reference)
#include <cuda_runtime.h>
#include <cstdint>

// Problem shape (fixed by reference setup_inputs)
#define Bn 4
#define Cn 32
#define Hn 480
#define Wn 854
#define HWn (Hn * Wn)
#define CHWn (Cn * HWn)

// ---------------------------------------------------------------------------
// Zero-init output (d_out is poisoned to 0xAA before timing).
// Vectorized float4 stores; out elements = 52,469,760 (divisible by 4).
// ---------------------------------------------------------------------------
__global__ void zero_kernel(float4* __restrict__ out, int n4) {
    int i = blockIdx.x * blockDim.x + threadIdx.x;
    int stride = gridDim.x * blockDim.x;
    for (; i < n4; i += stride) {
        out[i] = make_float4(0.f, 0.f, 0.f, 0.f);
    }
}

// ---------------------------------------------------------------------------
// Forward bilinear splat.
// One thread per source pixel (b, y, x). Corner targets + weights computed
// once, then a 32-channel loop does coalesced im0 loads and scattered RED
// adds. When x0 is even, the row-pair of corners (x0, x0+1) is in-bounds
// together (W even) and 8B-aligned -> a single red.global.add.v2.f32 per row
// replaces two scalar atomics.
// ---------------------------------------------------------------------------
__global__ void __launch_bounds__(256) splat_kernel(
    const float*  __restrict__ im0,
    const float2* __restrict__ flow,
    float*        __restrict__ out)
{
    const int pix = blockIdx.x * blockDim.x + threadIdx.x;
    if (pix >= Bn * HWn) return;

    const int b = pix / HWn;
    const int p = pix - b * HWn;
    const int y = p / Wn;
    const int x = p - y * Wn;

    const float2 f = flow[pix];
    const float tx = (float)x + f.x;
    const float ty = (float)y + f.y;

    const float x0f = floorf(tx);
    const float y0f = floorf(ty);
    const float fx = tx - x0f;
    const float fy = ty - y0f;

    const int x0 = (int)x0f;
    const int y0 = (int)y0f;
    const int x1 = x0 + 1;
    const int y1 = y0 + 1;

    const float gx = 1.f - fx;
    const float gy = 1.f - fy;
    const float w00 = gx * gy;   // (y0, x0)
    const float w01 = fx * gy;   // (y0, x1)
    const float w10 = gx * fy;   // (y1, x0)
    const float w11 = fx * fy;   // (y1, x1)

    const bool vy0 = (y0 >= 0) && (y0 < Hn);
    const bool vy1 = (y1 >= 0) && (y1 < Hn);
    const bool vx0 = (x0 >= 0) && (x0 < Wn);
    const bool vx1 = (x1 >= 0) && (x1 < Wn);

    // Even x0 in [0, W-1]: since W is even, x0 <= W-2 so (x0, x1) both valid,
    // and the pair is 8-byte aligned (row offsets even, base 256B aligned).
    const bool evenpair = ((x0 & 1) == 0) && vx0;

    const float* __restrict__ src = im0 + (size_t)b * CHWn + p;  // +c*HW per ch
    float* __restrict__ dstb = out + (size_t)b * CHWn;

    const int o00 = y0 * Wn + x0;  // may be garbage when invalid; guarded
    const int o10 = y1 * Wn + x0;

    #pragma unroll 4
    for (int c = 0; c < Cn; c++) {
        const float v = src[(size_t)c * HWn];
        float* __restrict__ pl = dstb + (size_t)c * HWn;
        if (evenpair) {
            if (vy0) {
                asm volatile("red.global.add.v2.f32 [%0], {%1, %2};"
                             :: "l"(pl + o00), "f"(w00 * v), "f"(w01 * v)
                             : "memory");
            }
            if (vy1) {
                asm volatile("red.global.add.v2.f32 [%0], {%1, %2};"
                             :: "l"(pl + o10), "f"(w10 * v), "f"(w11 * v)
                             : "memory");
            }
        } else {
            if (vy0 && vx0) atomicAdd(pl + o00,     w00 * v);
            if (vy0 && vx1) atomicAdd(pl + o00 + 1, w01 * v);
            if (vy1 && vx0) atomicAdd(pl + o10,     w10 * v);
            if (vy1 && vx1) atomicAdd(pl + o10 + 1, w11 * v);
        }
    }
}

// ---------------------------------------------------------------------------
// Harness entry. Two launches: zero-init, then splat. Graph-capturable:
// kernel launches only, no allocs, no syncs.
// ---------------------------------------------------------------------------
extern "C" void kernel_launch(void* const* d_in, const int* in_sizes, int n_in,
                              void* d_out, int out_size) {
    const float*  im0  = (const float*)d_in[0];
    const float2* flow = (const float2*)d_in[1];
    float* out = (float*)d_out;

    const int n4 = out_size / 4;
    zero_kernel<<<(n4 + 1023) / 1024, 256>>>((float4*)out, n4);

    const int npix = Bn * HWn;
    splat_kernel<<<(npix + 255) / 256, 256>>>(im0, flow, out);
}